// round 13
// baseline (speedup 1.0000x reference)
#include <cuda_runtime.h>
#include <cuda_bf16.h>
#include <cstdint>

#define BATCH 4
#define CIN   64
#define HH    128
#define WW    128
#define COUT  128
#define HW    (HH*WW)        // 16384
#define NPX   (BATCH*HW)     // 65536

// ---------------- scratch (device globals; no allocation allowed) ----------------
__device__ float  g_xt[BATCH*HW*CIN];     // x transposed to NHWC fp32: [b][h][w][c]
__device__ __align__(16) __nv_bfloat16 g_xbh[BATCH*HW*CIN];  // x NHWC bf16 hi
__device__ __align__(16) __nv_bfloat16 g_xbl[BATCH*HW*CIN];  // x NHWC bf16 lo
__device__ int    g_ppi[9*NPX];           // packed clamped corner coords per (k, pixel)
__device__ float4 g_ppw[9*NPX];           // bilinear weights (mask+validity folded)
// main weights split hi/lo, padded pitch-72 layout: [k][o][72] bf16
__device__ __align__(16) __nv_bfloat16 g_wbh[9*128*72];
__device__ __align__(16) __nv_bfloat16 g_wbl[9*128*72];
// offset/mask conv weights split hi/lo: [k][32][72] bf16 (rows 0-17 w_off, 18-26 w_mask, rest 0)
__device__ __align__(16) __nv_bfloat16 g_obh[9*32*72];
__device__ __align__(16) __nv_bfloat16 g_obl[9*32*72];

// ---------------- helpers ----------------
__device__ __forceinline__ uint32_t smem_u32(const void* p) {
    uint32_t a;
    asm("{ .reg .u64 t; cvta.to.shared.u64 t, %1; cvt.u32.u64 %0, t; }" : "=r"(a) : "l"(p));
    return a;
}
__device__ __forceinline__ void ldsm_x4(uint32_t (&r)[4], uint32_t addr) {
    asm volatile("ldmatrix.sync.aligned.m8n8.x4.shared.b16 {%0, %1, %2, %3}, [%4];"
                 : "=r"(r[0]), "=r"(r[1]), "=r"(r[2]), "=r"(r[3]) : "r"(addr));
}
__device__ __forceinline__ void mma16816(float (&d)[4], const uint32_t (&a)[4],
                                         uint32_t b0, uint32_t b1) {
    asm volatile(
        "mma.sync.aligned.m16n8k16.row.col.f32.bf16.bf16.f32 "
        "{%0, %1, %2, %3}, {%4, %5, %6, %7}, {%8, %9}, {%0, %1, %2, %3};"
        : "+f"(d[0]), "+f"(d[1]), "+f"(d[2]), "+f"(d[3])
        : "r"(a[0]), "r"(a[1]), "r"(a[2]), "r"(a[3]), "r"(b0), "r"(b1));
}
__device__ __forceinline__ void cp_async16(uint32_t saddr, const void* g) {
    asm volatile("cp.async.cg.shared.global [%0], [%1], 16;" :: "r"(saddr), "l"(g));
}
__device__ __forceinline__ void cp_async16z(uint32_t saddr, const void* g, uint32_t srcsz) {
    asm volatile("cp.async.cg.shared.global [%0], [%1], 16, %2;" :: "r"(saddr), "l"(g), "r"(srcsz));
}

// ---------------- kernel: transpose x (NCHW -> NHWC fp32 + bf16 hi/lo) ----------------
__global__ __launch_bounds__(256) void k_transpose_x(const float* __restrict__ x) {
    __shared__ float tile[64*129];
    int bid = blockIdx.x;              // b*128 + h
    int b = bid >> 7, h = bid & 127;
    int t = threadIdx.x;
    const float* xp = x + ((size_t)b*64*HW) + (size_t)h*WW;
    for (int i = t; i < 64*128; i += 256) {
        int c = i >> 7, w = i & 127;
        tile[c*129 + w] = xp[(size_t)c*HW + w];
    }
    __syncthreads();
    float4* out4 = (float4*)g_xt;
    uint2* oh = (uint2*)g_xbh;
    uint2* ol = (uint2*)g_xbl;
    for (int i = t; i < 2048; i += 256) {
        int w = i >> 4, cq = i & 15;
        float4 v;
        v.x = tile[(cq*4+0)*129 + w];
        v.y = tile[(cq*4+1)*129 + w];
        v.z = tile[(cq*4+2)*129 + w];
        v.w = tile[(cq*4+3)*129 + w];
        size_t oidx = (size_t)(bid*128 + w)*16 + cq;
        out4[oidx] = v;
        __nv_bfloat16 hx = __float2bfloat16_rn(v.x), hy = __float2bfloat16_rn(v.y);
        __nv_bfloat16 hz = __float2bfloat16_rn(v.z), hw = __float2bfloat16_rn(v.w);
        __nv_bfloat16 lx = __float2bfloat16_rn(v.x - __bfloat162float(hx));
        __nv_bfloat16 ly = __float2bfloat16_rn(v.y - __bfloat162float(hy));
        __nv_bfloat16 lz = __float2bfloat16_rn(v.z - __bfloat162float(hz));
        __nv_bfloat16 lw = __float2bfloat16_rn(v.w - __bfloat162float(hw));
        uint32_t h01 = ((uint32_t)__bfloat16_as_ushort(hy) << 16) | __bfloat16_as_ushort(hx);
        uint32_t h23 = ((uint32_t)__bfloat16_as_ushort(hw) << 16) | __bfloat16_as_ushort(hz);
        uint32_t l01 = ((uint32_t)__bfloat16_as_ushort(ly) << 16) | __bfloat16_as_ushort(lx);
        uint32_t l23 = ((uint32_t)__bfloat16_as_ushort(lw) << 16) | __bfloat16_as_ushort(lz);
        oh[oidx] = make_uint2(h01, h23);
        ol[oidx] = make_uint2(l01, l23);
    }
}

// ---------------- kernel: weight split hi/lo (main + offset/mask) ----------------
__global__ __launch_bounds__(256) void k_wsplit(
    const float* __restrict__ weight,
    const float* __restrict__ w_off, const float* __restrict__ w_mask) {
    int idx = blockIdx.x*256 + threadIdx.x;
    if (idx < 9*128*72) {
        int k = idx / 9216;
        int r = idx - k*9216;
        int o = r / 72, c = r - o*72;
        float v = (c < 64) ? weight[(o*64 + c)*9 + k] : 0.f;
        __nv_bfloat16 hi = __float2bfloat16_rn(v);
        __nv_bfloat16 lo = __float2bfloat16_rn(v - __bfloat162float(hi));
        g_wbh[idx] = hi;
        g_wbl[idx] = lo;
    } else if (idx < 9*128*72 + 9*32*72) {
        int i2 = idx - 9*128*72;
        int k = i2 / 2304;
        int r = i2 - k*2304;
        int o = r / 72, c = r - o*72;
        float v = 0.f;
        if (c < 64) {
            if (o < 18)      v = w_off[(o*64 + c)*9 + k];
            else if (o < 27) v = w_mask[((o-18)*64 + c)*9 + k];
        }
        __nv_bfloat16 hi = __float2bfloat16_rn(v);
        __nv_bfloat16 lo = __float2bfloat16_rn(v - __bfloat162float(hi));
        g_obh[i2] = hi;
        g_obl[i2] = lo;
    }
}

// ---------------- kernel: offset/mask conv via bf16 split MMA + epi ----------------
// grid 512 (b*128+h), 256 threads. M=128 px, N=32 (27 used), K=576 over 9 taps.
#define OBUF 46080
#define OB_AHI 0
#define OB_ALO 18432
#define OB_BHI 36864
#define OB_BLO 41472
#define OSMEM_TOT 92160

__global__ __launch_bounds__(256, 2) void k_offset_mma(
    const float* __restrict__ b_off, const float* __restrict__ b_mask)
{
    extern __shared__ char sm[];
    uint32_t sb = smem_u32(sm);
    int t   = threadIdx.x;
    int wid = t >> 5, lane = t & 31;
    int bid = blockIdx.x;              // b*128 + h
    int b = bid >> 7, h = bid & 127;

    float acc[4][4];
    #pragma unroll
    for (int i = 0; i < 4; ++i)
        #pragma unroll
        for (int q = 0; q < 4; ++q) acc[i][q] = 0.f;

    int lrow = (lane & 7) + ((lane >> 3) & 1) * 8;
    int lcol = (lane & 16) ? 8 : 0;

    auto stage = [&](int kk) {
        uint32_t base = sb + (kk & 1) * OBUF;
        int ky = kk / 3, kx = kk % 3;
        int hy = h - 1 + ky;
        bool rowok = (unsigned)hy < 128u;
        int hyc = rowok ? hy : 0;
        const char* srcH = (const char*)g_xbh + ((size_t)((b*128 + hyc)*128)) * 128;
        const char* srcL = (const char*)g_xbl + ((size_t)((b*128 + hyc)*128)) * 128;
        #pragma unroll
        for (int j = 0; j < 8; ++j) {
            int i = t + j*256;
            int half = i >> 10;
            int r = i & 1023;
            int px = r >> 3, part = r & 7;
            int sx = px - 1 + kx;
            bool ok = rowok && ((unsigned)sx < 128u);
            int sxc = ok ? sx : 0;
            uint32_t srcsz = ok ? 16u : 0u;
            const char* src = (half ? srcL : srcH) + (size_t)sxc*128 + part*16;
            uint32_t dst = base + (half ? OB_ALO : OB_AHI) + px*144 + part*16;
            cp_async16z(dst, src, srcsz);
        }
        #pragma unroll
        for (int j = 0; j < 3; ++j) {
            int i = t + j*256;
            if (i < 576) {
                int half = (i >= 288);
                int r = half ? i - 288 : i;
                const char* src = (const char*)(half ? g_obl : g_obh) + (size_t)kk*4608 + r*16;
                uint32_t dst = base + (half ? OB_BLO : OB_BHI) + r*16;
                cp_async16(dst, src);
            }
        }
        asm volatile("cp.async.commit_group;");
    };

    stage(0);
    for (int k = 0; k < 9; ++k) {
        asm volatile("cp.async.wait_group 0;" ::: "memory");
        __syncthreads();
        if (k < 8) stage(k + 1);
        uint32_t base = sb + (k & 1) * OBUF;
        #pragma unroll
        for (int ks = 0; ks < 4; ++ks) {
            int kc = ks*16 + lcol;
            uint32_t ah[4], al[4];
            uint32_t aoff = (uint32_t)((wid*16 + lrow)*144 + kc*2);
            ldsm_x4(ah, base + OB_AHI + aoff);
            ldsm_x4(al, base + OB_ALO + aoff);
            #pragma unroll
            for (int bt = 0; bt < 2; ++bt) {
                uint32_t bh[4], bl[4];
                uint32_t boff = (uint32_t)((bt*16 + lrow)*144 + kc*2);
                ldsm_x4(bh, base + OB_BHI + boff);
                ldsm_x4(bl, base + OB_BLO + boff);
                mma16816(acc[2*bt],   ah, bh[0], bh[2]);
                mma16816(acc[2*bt+1], ah, bh[1], bh[3]);
                mma16816(acc[2*bt],   al, bh[0], bh[2]);
                mma16816(acc[2*bt+1], al, bh[1], bh[3]);
                mma16816(acc[2*bt],   ah, bl[0], bl[2]);
                mma16816(acc[2*bt+1], ah, bl[1], bl[3]);
            }
        }
    }

    __syncthreads();
    float* smo = (float*)sm;
    int qrow = lane >> 2, qcol = (lane & 3) * 2;
    #pragma unroll
    for (int oct = 0; oct < 4; ++oct) {
        int co = oct*8 + qcol;
        if (co < 27) {
            int px0 = wid*16 + qrow;
            smo[px0*28 + co]     = acc[oct][0];
            smo[(px0+8)*28 + co] = acc[oct][2];
            if (co + 1 < 27) {
                smo[px0*28 + co + 1]     = acc[oct][1];
                smo[(px0+8)*28 + co + 1] = acc[oct][3];
            }
        }
    }
    __syncthreads();

    if (t < 128) {
        int px = t;
        int pxg = ((b << 7) + h)*128 + px;
        #pragma unroll
        for (int kk = 0; kk < 9; ++kk) {
            float dy = smo[px*28 + 2*kk]   + b_off[2*kk];
            float dx = smo[px*28 + 2*kk+1] + b_off[2*kk+1];
            float mz = smo[px*28 + 18+kk]  + b_mask[kk];
            float m  = 1.0f / (1.0f + __expf(-mz));
            float py  = (float)(h  - 1 + kk/3) + dy;
            float pxx = (float)(px - 1 + kk%3) + dx;
            float y0f = floorf(py), x0f = floorf(pxx);
            float ly = py - y0f, lx = pxx - x0f;
            int y0 = (int)y0f, x0i = (int)x0f;
            int y1 = y0 + 1,  x1i = x0i + 1;
            float w00 = (1.f-ly)*(1.f-lx)*m;
            float w01 = (1.f-ly)*lx*m;
            float w10 = ly*(1.f-lx)*m;
            float w11 = ly*lx*m;
            if (y0  < 0 || y0  > 127) { w00 = 0.f; w01 = 0.f; }
            if (y1  < 0 || y1  > 127) { w10 = 0.f; w11 = 0.f; }
            if (x0i < 0 || x0i > 127) { w00 = 0.f; w10 = 0.f; }
            if (x1i < 0 || x1i > 127) { w01 = 0.f; w11 = 0.f; }
            int y0c = min(max(y0, 0), 127),  y1c = min(max(y1, 0), 127);
            int x0c = min(max(x0i, 0), 127), x1c = min(max(x1i, 0), 127);
            g_ppi[kk*NPX + pxg] = y0c | (y1c << 8) | (x0c << 16) | (x1c << 24);
            g_ppw[kk*NPX + pxg] = make_float4(w00, w01, w10, w11);
        }
    }
}

// ---------------- kernel: deformable sampling + bf16 split mma.sync GEMM ----------------
// grid 1024 (b, h, half-row), 256 threads. Block tile: M=64 px, N=128 out, K=576. 3 CTAs/SM.
// Sampling layout: thread -> (chanquad = t&15, px = t>>4 + 16g). A warp-wide corner LDG.128
// reads two pixels' full 256-B corner rows -> 4 L1 wavefronts (optimal) vs 8 before.
#define SA_HI 0
#define SA_LO 9216
#define SB_HI 18432
#define SB_LO 36864
#define SMEM_TOT 55296

__global__ __launch_bounds__(256, 3) void k_deform_mma(float* __restrict__ out) {
    extern __shared__ char sm[];
    uint32_t sb = smem_u32(sm);
    int t    = threadIdx.x;
    int wid  = t >> 5, lane = t & 31;
    int bid  = blockIdx.x;                 // b*256 + h*2 + half
    int b    = bid >> 8;
    int rem  = bid & 255;
    int h    = rem >> 1, half = rem & 1;
    const float* xb = g_xt + ((size_t)b << 20);

    int warp_m = wid & 1;
    int warp_n = wid >> 1;
    int m0base = warp_m * 32;
    int n0base = warp_n * 32;

    float acc[2][4][4];
    #pragma unroll
    for (int i = 0; i < 2; ++i)
        #pragma unroll
        for (int j = 0; j < 4; ++j)
            #pragma unroll
            for (int q = 0; q < 4; ++q) acc[i][j][q] = 0.f;

    int lrow = (lane & 7) + ((lane >> 3) & 1) * 8;
    int lcol = (lane & 16) ? 8 : 0;

    int scq = t & 15;            // channel quad 0..15 (16 B each)
    int spx0 = t >> 4;           // base pixel 0..15

    for (int k = 0; k < 9; ++k) {
        __syncthreads();
        // ---- stage B tiles via cp.async (overlaps with the gather phase below) ----
        {
            const char* srcH = (const char*)(g_wbh + k*9216);
            const char* srcL = (const char*)(g_wbl + k*9216);
            #pragma unroll
            for (int j = 0; j < 4; ++j) {
                int i = t + j*256;
                cp_async16(sb + SB_HI + i*16, srcH + i*16);
            }
            #pragma unroll
            for (int j = 0; j < 4; ++j) {
                int i = t + j*256;
                cp_async16(sb + SB_LO + i*16, srcL + i*16);
            }
            if (t < 128) {
                int i = 1024 + t;
                cp_async16(sb + SB_HI + i*16, srcH + i*16);
                cp_async16(sb + SB_LO + i*16, srcL + i*16);
            }
            asm volatile("cp.async.commit_group;");
        }
        // ---- sampling: 16 lanes per pixel, 4 pixels per thread ----
        {
            int ppb = k*NPX + (((b << 7) + h) << 7) + half*64;
            #pragma unroll
            for (int g = 0; g < 4; ++g) {
                int px = spx0 + g*16;
                int    pc = g_ppi[ppb + px];     // broadcast across 16 lanes
                float4 wg = g_ppw[ppb + px];
                int y0 =  pc        & 255;
                int y1 = (pc >>  8) & 255;
                int x0 = (pc >> 16) & 255;
                int x1 = (pc >> 24) & 255;
                float4 a  = *((const float4*)(xb + (size_t)(((y0<<7)+x0)<<6)) + scq);
                float4 bb = *((const float4*)(xb + (size_t)(((y0<<7)+x1)<<6)) + scq);
                float4 cc = *((const float4*)(xb + (size_t)(((y1<<7)+x0)<<6)) + scq);
                float4 dd = *((const float4*)(xb + (size_t)(((y1<<7)+x1)<<6)) + scq);
                float4 v;
                v.x = wg.x*a.x + wg.y*bb.x + wg.z*cc.x + wg.w*dd.x;
                v.y = wg.x*a.y + wg.y*bb.y + wg.z*cc.y + wg.w*dd.y;
                v.z = wg.x*a.z + wg.y*bb.z + wg.z*cc.z + wg.w*dd.z;
                v.w = wg.x*a.w + wg.y*bb.w + wg.z*cc.w + wg.w*dd.w;
                __nv_bfloat16 hx = __float2bfloat16_rn(v.x), hy = __float2bfloat16_rn(v.y);
                __nv_bfloat16 hz = __float2bfloat16_rn(v.z), hw = __float2bfloat16_rn(v.w);
                __nv_bfloat16 lx2 = __float2bfloat16_rn(v.x - __bfloat162float(hx));
                __nv_bfloat16 ly2 = __float2bfloat16_rn(v.y - __bfloat162float(hy));
                __nv_bfloat16 lz2 = __float2bfloat16_rn(v.z - __bfloat162float(hz));
                __nv_bfloat16 lw2 = __float2bfloat16_rn(v.w - __bfloat162float(hw));
                uint32_t h01 = ((uint32_t)__bfloat16_as_ushort(hy) << 16) | __bfloat16_as_ushort(hx);
                uint32_t h23 = ((uint32_t)__bfloat16_as_ushort(hw) << 16) | __bfloat16_as_ushort(hz);
                uint32_t l01 = ((uint32_t)__bfloat16_as_ushort(ly2) << 16) | __bfloat16_as_ushort(lx2);
                uint32_t l23 = ((uint32_t)__bfloat16_as_ushort(lw2) << 16) | __bfloat16_as_ushort(lz2);
                int off = px*144 + scq*8;
                *(uint2*)(sm + SA_HI + off) = make_uint2(h01, h23);
                *(uint2*)(sm + SA_LO + off) = make_uint2(l01, l23);
            }
        }
        asm volatile("cp.async.wait_group 0;" ::: "memory");
        __syncthreads();

        // ---- MMA: 4 ksteps of 16, split passes ----
        #pragma unroll
        for (int ks = 0; ks < 4; ++ks) {
            int kc = ks*16 + lcol;
            uint32_t ah[2][4], al[2][4];
            #pragma unroll
            for (int mt = 0; mt < 2; ++mt) {
                uint32_t aoff = (uint32_t)((m0base + mt*16 + lrow)*144 + kc*2);
                ldsm_x4(ah[mt], sb + SA_HI + aoff);
                ldsm_x4(al[mt], sb + SA_LO + aoff);
            }
            #pragma unroll
            for (int ng = 0; ng < 2; ++ng) {
                uint32_t bh[4], bl[4];
                uint32_t boff = (uint32_t)((n0base + ng*16 + lrow)*144 + kc*2);
                ldsm_x4(bh, sb + SB_HI + boff);
                ldsm_x4(bl, sb + SB_LO + boff);
                #pragma unroll
                for (int mt = 0; mt < 2; ++mt) {
                    mma16816(acc[mt][2*ng],   ah[mt], bh[0], bh[2]);
                    mma16816(acc[mt][2*ng+1], ah[mt], bh[1], bh[3]);
                    mma16816(acc[mt][2*ng],   al[mt], bh[0], bh[2]);
                    mma16816(acc[mt][2*ng+1], al[mt], bh[1], bh[3]);
                    mma16816(acc[mt][2*ng],   ah[mt], bl[0], bl[2]);
                    mma16816(acc[mt][2*ng+1], ah[mt], bl[1], bl[3]);
                }
            }
        }
    }

    // ---- epilogue: frags -> smem [o][px] (pitch 68), coalesced stores ----
    __syncthreads();
    float* smo = (float*)sm;
    int qrow = lane >> 2, qcol = (lane & 3) * 2;
    #pragma unroll
    for (int mt = 0; mt < 2; ++mt) {
        #pragma unroll
        for (int nt = 0; nt < 4; ++nt) {
            int px0 = m0base + mt*16 + qrow;
            int o0  = n0base + nt*8 + qcol;
            smo[ o0     *68 + px0    ] = acc[mt][nt][0];
            smo[(o0 + 1)*68 + px0    ] = acc[mt][nt][1];
            smo[ o0     *68 + px0 + 8] = acc[mt][nt][2];
            smo[(o0 + 1)*68 + px0 + 8] = acc[mt][nt][3];
        }
    }
    __syncthreads();
    float* op = out + ((size_t)b*128)*16384 + (size_t)h*128 + half*64;
    #pragma unroll
    for (int j = 0; j < 8; ++j) {
        int idx = t + j*256;
        int o = idx >> 4, pq = idx & 15;
        float4 v = *(const float4*)(smo + o*68 + pq*4);
        *(float4*)(op + (size_t)o*16384 + pq*4) = v;
    }
}

// ---------------- launch ----------------
extern "C" void kernel_launch(void* const* d_in, const int* in_sizes, int n_in,
                              void* d_out, int out_size) {
    const float* x      = (const float*)d_in[0];
    const float* w_off  = (const float*)d_in[1];
    const float* b_off  = (const float*)d_in[2];
    const float* w_mask = (const float*)d_in[3];
    const float* b_mask = (const float*)d_in[4];
    const float* weight = (const float*)d_in[5];
    float* out = (float*)d_out;

    (void)cudaFuncSetAttribute(k_deform_mma, cudaFuncAttributeMaxDynamicSharedMemorySize, SMEM_TOT);
    (void)cudaFuncSetAttribute(k_offset_mma, cudaFuncAttributeMaxDynamicSharedMemorySize, OSMEM_TOT);

    k_transpose_x<<<512, 256>>>(x);
    k_wsplit<<<(9*128*72 + 9*32*72 + 255)/256, 256>>>(weight, w_off, w_mask);
    k_offset_mma<<<512, 256, OSMEM_TOT>>>(b_off, b_mask);
    k_deform_mma<<<1024, 256, SMEM_TOT>>>(out);
}

// round 16
// speedup vs baseline: 1.0696x; 1.0696x over previous
#include <cuda_runtime.h>
#include <cuda_bf16.h>
#include <cstdint>

#define BATCH 4
#define CIN   64
#define HH    128
#define WW    128
#define COUT  128
#define HW    (HH*WW)        // 16384
#define NPX   (BATCH*HW)     // 65536

// ---------------- scratch (device globals; no allocation allowed) ----------------
__device__ float  g_xt[BATCH*HW*CIN];     // x transposed to NHWC fp32: [b][h][w][c]
__device__ __align__(16) __nv_bfloat16 g_xbh[BATCH*HW*CIN];  // x NHWC bf16 hi
__device__ __align__(16) __nv_bfloat16 g_xbl[BATCH*HW*CIN];  // x NHWC bf16 lo
__device__ int    g_ppi[9*NPX];           // packed clamped corner coords per (k, pixel)
__device__ float4 g_ppw[9*NPX];           // bilinear weights (mask+validity folded)
// main weights split hi/lo, padded pitch-72 layout: [k][o][72] bf16
__device__ __align__(16) __nv_bfloat16 g_wbh[9*128*72];
__device__ __align__(16) __nv_bfloat16 g_wbl[9*128*72];
// offset/mask conv weights split hi/lo: [k][32][72] bf16 (rows 0-17 w_off, 18-26 w_mask, rest 0)
__device__ __align__(16) __nv_bfloat16 g_obh[9*32*72];
__device__ __align__(16) __nv_bfloat16 g_obl[9*32*72];

// ---------------- helpers ----------------
__device__ __forceinline__ uint32_t smem_u32(const void* p) {
    uint32_t a;
    asm("{ .reg .u64 t; cvta.to.shared.u64 t, %1; cvt.u32.u64 %0, t; }" : "=r"(a) : "l"(p));
    return a;
}
__device__ __forceinline__ void ldsm_x4(uint32_t (&r)[4], uint32_t addr) {
    asm volatile("ldmatrix.sync.aligned.m8n8.x4.shared.b16 {%0, %1, %2, %3}, [%4];"
                 : "=r"(r[0]), "=r"(r[1]), "=r"(r[2]), "=r"(r[3]) : "r"(addr));
}
__device__ __forceinline__ void mma16816(float (&d)[4], const uint32_t (&a)[4],
                                         uint32_t b0, uint32_t b1) {
    asm volatile(
        "mma.sync.aligned.m16n8k16.row.col.f32.bf16.bf16.f32 "
        "{%0, %1, %2, %3}, {%4, %5, %6, %7}, {%8, %9}, {%0, %1, %2, %3};"
        : "+f"(d[0]), "+f"(d[1]), "+f"(d[2]), "+f"(d[3])
        : "r"(a[0]), "r"(a[1]), "r"(a[2]), "r"(a[3]), "r"(b0), "r"(b1));
}
__device__ __forceinline__ void cp_async16(uint32_t saddr, const void* g) {
    asm volatile("cp.async.cg.shared.global [%0], [%1], 16;" :: "r"(saddr), "l"(g));
}
__device__ __forceinline__ void cp_async16z(uint32_t saddr, const void* g, uint32_t srcsz) {
    asm volatile("cp.async.cg.shared.global [%0], [%1], 16, %2;" :: "r"(saddr), "l"(g), "r"(srcsz));
}

// ---------------- kernel: transpose x (NCHW -> NHWC fp32 + bf16 hi/lo) ----------------
__global__ __launch_bounds__(256) void k_transpose_x(const float* __restrict__ x) {
    __shared__ float tile[64*129];
    int bid = blockIdx.x;              // b*128 + h
    int b = bid >> 7, h = bid & 127;
    int t = threadIdx.x;
    const float* xp = x + ((size_t)b*64*HW) + (size_t)h*WW;
    for (int i = t; i < 64*128; i += 256) {
        int c = i >> 7, w = i & 127;
        tile[c*129 + w] = xp[(size_t)c*HW + w];
    }
    __syncthreads();
    float4* out4 = (float4*)g_xt;
    uint2* oh = (uint2*)g_xbh;
    uint2* ol = (uint2*)g_xbl;
    for (int i = t; i < 2048; i += 256) {
        int w = i >> 4, cq = i & 15;
        float4 v;
        v.x = tile[(cq*4+0)*129 + w];
        v.y = tile[(cq*4+1)*129 + w];
        v.z = tile[(cq*4+2)*129 + w];
        v.w = tile[(cq*4+3)*129 + w];
        size_t oidx = (size_t)(bid*128 + w)*16 + cq;
        out4[oidx] = v;
        __nv_bfloat16 hx = __float2bfloat16_rn(v.x), hy = __float2bfloat16_rn(v.y);
        __nv_bfloat16 hz = __float2bfloat16_rn(v.z), hw = __float2bfloat16_rn(v.w);
        __nv_bfloat16 lx = __float2bfloat16_rn(v.x - __bfloat162float(hx));
        __nv_bfloat16 ly = __float2bfloat16_rn(v.y - __bfloat162float(hy));
        __nv_bfloat16 lz = __float2bfloat16_rn(v.z - __bfloat162float(hz));
        __nv_bfloat16 lw = __float2bfloat16_rn(v.w - __bfloat162float(hw));
        uint32_t h01 = ((uint32_t)__bfloat16_as_ushort(hy) << 16) | __bfloat16_as_ushort(hx);
        uint32_t h23 = ((uint32_t)__bfloat16_as_ushort(hw) << 16) | __bfloat16_as_ushort(hz);
        uint32_t l01 = ((uint32_t)__bfloat16_as_ushort(ly) << 16) | __bfloat16_as_ushort(lx);
        uint32_t l23 = ((uint32_t)__bfloat16_as_ushort(lw) << 16) | __bfloat16_as_ushort(lz);
        oh[oidx] = make_uint2(h01, h23);
        ol[oidx] = make_uint2(l01, l23);
    }
}

// ---------------- kernel: weight split hi/lo (main + offset/mask) ----------------
__global__ __launch_bounds__(256) void k_wsplit(
    const float* __restrict__ weight,
    const float* __restrict__ w_off, const float* __restrict__ w_mask) {
    int idx = blockIdx.x*256 + threadIdx.x;
    if (idx < 9*128*72) {
        int k = idx / 9216;
        int r = idx - k*9216;
        int o = r / 72, c = r - o*72;
        float v = (c < 64) ? weight[(o*64 + c)*9 + k] : 0.f;
        __nv_bfloat16 hi = __float2bfloat16_rn(v);
        __nv_bfloat16 lo = __float2bfloat16_rn(v - __bfloat162float(hi));
        g_wbh[idx] = hi;
        g_wbl[idx] = lo;
    } else if (idx < 9*128*72 + 9*32*72) {
        int i2 = idx - 9*128*72;
        int k = i2 / 2304;
        int r = i2 - k*2304;
        int o = r / 72, c = r - o*72;
        float v = 0.f;
        if (c < 64) {
            if (o < 18)      v = w_off[(o*64 + c)*9 + k];
            else if (o < 27) v = w_mask[((o-18)*64 + c)*9 + k];
        }
        __nv_bfloat16 hi = __float2bfloat16_rn(v);
        __nv_bfloat16 lo = __float2bfloat16_rn(v - __bfloat162float(hi));
        g_obh[i2] = hi;
        g_obl[i2] = lo;
    }
}

// ---------------- kernel: offset/mask conv via bf16 split MMA + epi ----------------
// grid 512 (b*128+h), 256 threads. M=128 px, N=32 (27 used), K=576 over 9 taps.
#define OBUF 46080
#define OB_AHI 0
#define OB_ALO 18432
#define OB_BHI 36864
#define OB_BLO 41472
#define OSMEM_TOT 92160

__global__ __launch_bounds__(256, 2) void k_offset_mma(
    const float* __restrict__ b_off, const float* __restrict__ b_mask)
{
    extern __shared__ char sm[];
    uint32_t sb = smem_u32(sm);
    int t   = threadIdx.x;
    int wid = t >> 5, lane = t & 31;
    int bid = blockIdx.x;              // b*128 + h
    int b = bid >> 7, h = bid & 127;

    float acc[4][4];
    #pragma unroll
    for (int i = 0; i < 4; ++i)
        #pragma unroll
        for (int q = 0; q < 4; ++q) acc[i][q] = 0.f;

    int lrow = (lane & 7) + ((lane >> 3) & 1) * 8;
    int lcol = (lane & 16) ? 8 : 0;

    auto stage = [&](int kk) {
        uint32_t base = sb + (kk & 1) * OBUF;
        int ky = kk / 3, kx = kk % 3;
        int hy = h - 1 + ky;
        bool rowok = (unsigned)hy < 128u;
        int hyc = rowok ? hy : 0;
        const char* srcH = (const char*)g_xbh + ((size_t)((b*128 + hyc)*128)) * 128;
        const char* srcL = (const char*)g_xbl + ((size_t)((b*128 + hyc)*128)) * 128;
        #pragma unroll
        for (int j = 0; j < 8; ++j) {
            int i = t + j*256;
            int half = i >> 10;
            int r = i & 1023;
            int px = r >> 3, part = r & 7;
            int sx = px - 1 + kx;
            bool ok = rowok && ((unsigned)sx < 128u);
            int sxc = ok ? sx : 0;
            uint32_t srcsz = ok ? 16u : 0u;
            const char* src = (half ? srcL : srcH) + (size_t)sxc*128 + part*16;
            uint32_t dst = base + (half ? OB_ALO : OB_AHI) + px*144 + part*16;
            cp_async16z(dst, src, srcsz);
        }
        #pragma unroll
        for (int j = 0; j < 3; ++j) {
            int i = t + j*256;
            if (i < 576) {
                int half = (i >= 288);
                int r = half ? i - 288 : i;
                const char* src = (const char*)(half ? g_obl : g_obh) + (size_t)kk*4608 + r*16;
                uint32_t dst = base + (half ? OB_BLO : OB_BHI) + r*16;
                cp_async16(dst, src);
            }
        }
        asm volatile("cp.async.commit_group;");
    };

    stage(0);
    for (int k = 0; k < 9; ++k) {
        asm volatile("cp.async.wait_group 0;" ::: "memory");
        __syncthreads();
        if (k < 8) stage(k + 1);
        uint32_t base = sb + (k & 1) * OBUF;
        #pragma unroll
        for (int ks = 0; ks < 4; ++ks) {
            int kc = ks*16 + lcol;
            uint32_t ah[4], al[4];
            uint32_t aoff = (uint32_t)((wid*16 + lrow)*144 + kc*2);
            ldsm_x4(ah, base + OB_AHI + aoff);
            ldsm_x4(al, base + OB_ALO + aoff);
            #pragma unroll
            for (int bt = 0; bt < 2; ++bt) {
                uint32_t bh[4], bl[4];
                uint32_t boff = (uint32_t)((bt*16 + lrow)*144 + kc*2);
                ldsm_x4(bh, base + OB_BHI + boff);
                ldsm_x4(bl, base + OB_BLO + boff);
                mma16816(acc[2*bt],   ah, bh[0], bh[2]);
                mma16816(acc[2*bt+1], ah, bh[1], bh[3]);
                mma16816(acc[2*bt],   al, bh[0], bh[2]);
                mma16816(acc[2*bt+1], al, bh[1], bh[3]);
                mma16816(acc[2*bt],   ah, bl[0], bl[2]);
                mma16816(acc[2*bt+1], ah, bl[1], bl[3]);
            }
        }
    }

    __syncthreads();
    float* smo = (float*)sm;
    int qrow = lane >> 2, qcol = (lane & 3) * 2;
    #pragma unroll
    for (int oct = 0; oct < 4; ++oct) {
        int co = oct*8 + qcol;
        if (co < 27) {
            int px0 = wid*16 + qrow;
            smo[px0*28 + co]     = acc[oct][0];
            smo[(px0+8)*28 + co] = acc[oct][2];
            if (co + 1 < 27) {
                smo[px0*28 + co + 1]     = acc[oct][1];
                smo[(px0+8)*28 + co + 1] = acc[oct][3];
            }
        }
    }
    __syncthreads();

    if (t < 128) {
        int px = t;
        int pxg = ((b << 7) + h)*128 + px;
        #pragma unroll
        for (int kk = 0; kk < 9; ++kk) {
            float dy = smo[px*28 + 2*kk]   + b_off[2*kk];
            float dx = smo[px*28 + 2*kk+1] + b_off[2*kk+1];
            float mz = smo[px*28 + 18+kk]  + b_mask[kk];
            float m  = 1.0f / (1.0f + __expf(-mz));
            float py  = (float)(h  - 1 + kk/3) + dy;
            float pxx = (float)(px - 1 + kk%3) + dx;
            float y0f = floorf(py), x0f = floorf(pxx);
            float ly = py - y0f, lx = pxx - x0f;
            int y0 = (int)y0f, x0i = (int)x0f;
            int y1 = y0 + 1,  x1i = x0i + 1;
            float w00 = (1.f-ly)*(1.f-lx)*m;
            float w01 = (1.f-ly)*lx*m;
            float w10 = ly*(1.f-lx)*m;
            float w11 = ly*lx*m;
            if (y0  < 0 || y0  > 127) { w00 = 0.f; w01 = 0.f; }
            if (y1  < 0 || y1  > 127) { w10 = 0.f; w11 = 0.f; }
            if (x0i < 0 || x0i > 127) { w00 = 0.f; w10 = 0.f; }
            if (x1i < 0 || x1i > 127) { w01 = 0.f; w11 = 0.f; }
            int y0c = min(max(y0, 0), 127),  y1c = min(max(y1, 0), 127);
            int x0c = min(max(x0i, 0), 127), x1c = min(max(x1i, 0), 127);
            g_ppi[kk*NPX + pxg] = y0c | (y1c << 8) | (x0c << 16) | (x1c << 24);
            g_ppw[kk*NPX + pxg] = make_float4(w00, w01, w10, w11);
        }
    }
}

// ---------------- kernel: deformable sampling + bf16 split mma.sync GEMM ----------------
// grid 1024 (b, h, half-row), 256 threads. Block tile: M=64 px, N=128 out, K=576.
// A and B tiles DOUBLE-BUFFERED; per-iteration: one sync, then barrier-free region where
// each thread interleaves (issue 4 corner LDGs for tap k+1) -> (MMA kstep j on tap k)
// -> (interp/store j into next A buffer). 2 CTAs/SM (smem 110592 B).
// NOTE: shared-space addresses (sb + ...) ONLY for ldsm/cp.async; generic stores use
// byte offsets on sm directly (R14 bug: sm + sb + off double-counted the base).
#define DA_STRIDE 18432      // per A buffer: HI 9216 + LO 9216
#define DA_LO 9216
#define DB_OFF 36864
#define DB_STRIDE 36864      // per B buffer: HI 18432 + LO 18432
#define DB_LO 18432
#define DSMEM_TOT 110592

__global__ __launch_bounds__(256, 2) void k_deform_mma(float* __restrict__ out) {
    extern __shared__ char sm[];
    uint32_t sb = smem_u32(sm);
    int t    = threadIdx.x;
    int wid  = t >> 5, lane = t & 31;
    int bid  = blockIdx.x;                 // b*256 + h*2 + half
    int b    = bid >> 8;
    int rem  = bid & 255;
    int h    = rem >> 1, half = rem & 1;
    const float* xb = g_xt + ((size_t)b << 20);

    int warp_m = wid & 1;
    int warp_n = wid >> 1;
    int m0base = warp_m * 32;
    int n0base = warp_n * 32;

    float acc[2][4][4];
    #pragma unroll
    for (int i = 0; i < 2; ++i)
        #pragma unroll
        for (int j = 0; j < 4; ++j)
            #pragma unroll
            for (int q = 0; q < 4; ++q) acc[i][j][q] = 0.f;

    int lrow = (lane & 7) + ((lane >> 3) & 1) * 8;
    int lcol = (lane & 16) ? 8 : 0;

    int spx = t >> 2, sq = t & 3;          // sampling: thread -> (pixel, chunk-quad), MLP=16
    int pxbase = (((b << 7) + h) << 7) + half*64;

    // stage B tap kk into B buffer kk&1 via cp.async (shared-space dst)
    auto stage_B = [&](int kk) {
        uint32_t bbuf = sb + DB_OFF + (kk & 1) * DB_STRIDE;
        const char* srcH = (const char*)(g_wbh + kk*9216);
        const char* srcL = (const char*)(g_wbl + kk*9216);
        #pragma unroll
        for (int j = 0; j < 5; ++j) {
            int i = t + j*256;
            if (i < 1152) {
                cp_async16(bbuf + i*16, srcH + i*16);
                cp_async16(bbuf + DB_LO + i*16, srcL + i*16);
            }
        }
        asm volatile("cp.async.commit_group;");
    };

    // sample helper: interp chunk, split, store into A buffer at byte offset abuf_off (generic)
    auto store_sample = [&](int abuf_off, int j, float4 a, float4 bb, float4 cc, float4 dd,
                            float4 wg) {
        float4 v;
        v.x = wg.x*a.x + wg.y*bb.x + wg.z*cc.x + wg.w*dd.x;
        v.y = wg.x*a.y + wg.y*bb.y + wg.z*cc.y + wg.w*dd.y;
        v.z = wg.x*a.z + wg.y*bb.z + wg.z*cc.z + wg.w*dd.z;
        v.w = wg.x*a.w + wg.y*bb.w + wg.z*cc.w + wg.w*dd.w;
        __nv_bfloat16 hx = __float2bfloat16_rn(v.x), hy = __float2bfloat16_rn(v.y);
        __nv_bfloat16 hz = __float2bfloat16_rn(v.z), hw = __float2bfloat16_rn(v.w);
        __nv_bfloat16 lx2 = __float2bfloat16_rn(v.x - __bfloat162float(hx));
        __nv_bfloat16 ly2 = __float2bfloat16_rn(v.y - __bfloat162float(hy));
        __nv_bfloat16 lz2 = __float2bfloat16_rn(v.z - __bfloat162float(hz));
        __nv_bfloat16 lw2 = __float2bfloat16_rn(v.w - __bfloat162float(hw));
        uint32_t h01 = ((uint32_t)__bfloat16_as_ushort(hy) << 16) | __bfloat16_as_ushort(hx);
        uint32_t h23 = ((uint32_t)__bfloat16_as_ushort(hw) << 16) | __bfloat16_as_ushort(hz);
        uint32_t l01 = ((uint32_t)__bfloat16_as_ushort(ly2) << 16) | __bfloat16_as_ushort(lx2);
        uint32_t l23 = ((uint32_t)__bfloat16_as_ushort(lw2) << 16) | __bfloat16_as_ushort(lz2);
        int off = spx*144 + (sq + 4*j)*8;
        *(uint2*)(sm + abuf_off + off) = make_uint2(h01, h23);
        *(uint2*)(sm + abuf_off + DA_LO + off) = make_uint2(l01, l23);
    };

    // prologue: B(0) async + full sample of tap 0 into A buffer 0 (byte offset 0)
    stage_B(0);
    {
        int    pc = g_ppi[pxbase + spx];
        float4 wg = g_ppw[pxbase + spx];
        int y0 =  pc        & 255;
        int y1 = (pc >>  8) & 255;
        int x0 = (pc >> 16) & 255;
        int x1 = (pc >> 24) & 255;
        const float4* r00 = (const float4*)(xb + (size_t)(((y0<<7)+x0)<<6)) + sq;
        const float4* r01 = (const float4*)(xb + (size_t)(((y0<<7)+x1)<<6)) + sq;
        const float4* r10 = (const float4*)(xb + (size_t)(((y1<<7)+x0)<<6)) + sq;
        const float4* r11 = (const float4*)(xb + (size_t)(((y1<<7)+x1)<<6)) + sq;
        #pragma unroll
        for (int j = 0; j < 4; ++j)
            store_sample(0, j, r00[4*j], r01[4*j], r10[4*j], r11[4*j], wg);
    }

    for (int k = 0; k < 9; ++k) {
        asm volatile("cp.async.wait_group 0;" ::: "memory");   // B(k) landed
        __syncthreads();                                       // A(k) published; prev reads of buf k^1 done
        if (k < 8) stage_B(k + 1);

        uint32_t abase = sb + (k & 1) * DA_STRIDE;             // shared addr (ldsm)
        uint32_t bbase = sb + DB_OFF + (k & 1) * DB_STRIDE;    // shared addr (ldsm)
        int an_off = ((k + 1) & 1) * DA_STRIDE;                // BYTE OFFSET (generic stores)

        bool do_sample = (k < 8);
        float4 wg;
        const float4 *r00 = nullptr, *r01 = nullptr, *r10 = nullptr, *r11 = nullptr;
        if (do_sample) {
            int ppb = (k + 1)*NPX + pxbase;
            int pc = g_ppi[ppb + spx];
            wg = g_ppw[ppb + spx];
            int y0 =  pc        & 255;
            int y1 = (pc >>  8) & 255;
            int x0 = (pc >> 16) & 255;
            int x1 = (pc >> 24) & 255;
            r00 = (const float4*)(xb + (size_t)(((y0<<7)+x0)<<6)) + sq;
            r01 = (const float4*)(xb + (size_t)(((y0<<7)+x1)<<6)) + sq;
            r10 = (const float4*)(xb + (size_t)(((y1<<7)+x0)<<6)) + sq;
            r11 = (const float4*)(xb + (size_t)(((y1<<7)+x1)<<6)) + sq;
        }

        #pragma unroll
        for (int j = 0; j < 4; ++j) {
            // (1) issue next-tap corner loads (long latency, independent of MMA)
            float4 a, bb, cc, dd;
            if (do_sample) { a = r00[4*j]; bb = r01[4*j]; cc = r10[4*j]; dd = r11[4*j]; }

            // (2) MMA kstep j on buffers k
            {
                int kc = j*16 + lcol;
                uint32_t ah[2][4], al[2][4];
                #pragma unroll
                for (int mt = 0; mt < 2; ++mt) {
                    uint32_t aoff = (uint32_t)((m0base + mt*16 + lrow)*144 + kc*2);
                    ldsm_x4(ah[mt], abase + aoff);
                    ldsm_x4(al[mt], abase + DA_LO + aoff);
                }
                #pragma unroll
                for (int ng = 0; ng < 2; ++ng) {
                    uint32_t bh[4], bl[4];
                    uint32_t boff = (uint32_t)((n0base + ng*16 + lrow)*144 + kc*2);
                    ldsm_x4(bh, bbase + boff);
                    ldsm_x4(bl, bbase + DB_LO + boff);
                    #pragma unroll
                    for (int mt = 0; mt < 2; ++mt) {
                        mma16816(acc[mt][2*ng],   ah[mt], bh[0], bh[2]);
                        mma16816(acc[mt][2*ng+1], ah[mt], bh[1], bh[3]);
                        mma16816(acc[mt][2*ng],   al[mt], bh[0], bh[2]);
                        mma16816(acc[mt][2*ng+1], al[mt], bh[1], bh[3]);
                        mma16816(acc[mt][2*ng],   ah[mt], bl[0], bl[2]);
                        mma16816(acc[mt][2*ng+1], ah[mt], bl[1], bl[3]);
                    }
                }
            }

            // (3) consume loads: interp, split, store into next A buffer (byte offset)
            if (do_sample)
                store_sample(an_off, j, a, bb, cc, dd, wg);
        }
    }

    // ---- epilogue: frags -> smem [o][px] (pitch 68), coalesced stores ----
    __syncthreads();
    float* smo = (float*)sm;
    int qrow = lane >> 2, qcol = (lane & 3) * 2;
    #pragma unroll
    for (int mt = 0; mt < 2; ++mt) {
        #pragma unroll
        for (int nt = 0; nt < 4; ++nt) {
            int px0 = m0base + mt*16 + qrow;
            int o0  = n0base + nt*8 + qcol;
            smo[ o0     *68 + px0    ] = acc[mt][nt][0];
            smo[(o0 + 1)*68 + px0    ] = acc[mt][nt][1];
            smo[ o0     *68 + px0 + 8] = acc[mt][nt][2];
            smo[(o0 + 1)*68 + px0 + 8] = acc[mt][nt][3];
        }
    }
    __syncthreads();
    float* op = out + ((size_t)b*128)*16384 + (size_t)h*128 + half*64;
    #pragma unroll
    for (int j = 0; j < 8; ++j) {
        int idx = t + j*256;
        int o = idx >> 4, pq = idx & 15;
        float4 v = *(const float4*)(smo + o*68 + pq*4);
        *(float4*)(op + (size_t)o*16384 + pq*4) = v;
    }
}

// ---------------- launch ----------------
extern "C" void kernel_launch(void* const* d_in, const int* in_sizes, int n_in,
                              void* d_out, int out_size) {
    const float* x      = (const float*)d_in[0];
    const float* w_off  = (const float*)d_in[1];
    const float* b_off  = (const float*)d_in[2];
    const float* w_mask = (const float*)d_in[3];
    const float* b_mask = (const float*)d_in[4];
    const float* weight = (const float*)d_in[5];
    float* out = (float*)d_out;

    (void)cudaFuncSetAttribute(k_deform_mma, cudaFuncAttributeMaxDynamicSharedMemorySize, DSMEM_TOT);
    (void)cudaFuncSetAttribute(k_offset_mma, cudaFuncAttributeMaxDynamicSharedMemorySize, OSMEM_TOT);

    k_transpose_x<<<512, 256>>>(x);
    k_wsplit<<<(9*128*72 + 9*32*72 + 255)/256, 256>>>(weight, w_off, w_mask);
    k_offset_mma<<<512, 256, OSMEM_TOT>>>(b_off, b_mask);
    k_deform_mma<<<1024, 256, DSMEM_TOT>>>(out);
}

// round 17
// speedup vs baseline: 1.0832x; 1.0128x over previous
#include <cuda_runtime.h>
#include <cuda_bf16.h>
#include <cstdint>

#define BATCH 4
#define CIN   64
#define HH    128
#define WW    128
#define COUT  128
#define HW    (HH*WW)        // 16384
#define NPX   (BATCH*HW)     // 65536

// ---------------- scratch (device globals; no allocation allowed) ----------------
__device__ float  g_xt[BATCH*HW*CIN];     // x transposed to NHWC fp32: [b][h][w][c]
__device__ __align__(16) __nv_bfloat16 g_xbh[BATCH*HW*CIN];  // x NHWC bf16 hi
__device__ __align__(16) __nv_bfloat16 g_xbl[BATCH*HW*CIN];  // x NHWC bf16 lo
__device__ int    g_ppi[9*NPX];           // packed clamped corner coords per (k, pixel)
__device__ float4 g_ppw[9*NPX];           // bilinear weights (mask+validity folded)
// main weights split hi/lo, padded pitch-72 layout: [k][o][72] bf16
__device__ __align__(16) __nv_bfloat16 g_wbh[9*128*72];
__device__ __align__(16) __nv_bfloat16 g_wbl[9*128*72];
// offset/mask conv weights split hi/lo: [k][32][72] bf16 (rows 0-17 w_off, 18-26 w_mask, rest 0)
__device__ __align__(16) __nv_bfloat16 g_obh[9*32*72];
__device__ __align__(16) __nv_bfloat16 g_obl[9*32*72];

// ---------------- helpers ----------------
__device__ __forceinline__ uint32_t smem_u32(const void* p) {
    uint32_t a;
    asm("{ .reg .u64 t; cvta.to.shared.u64 t, %1; cvt.u32.u64 %0, t; }" : "=r"(a) : "l"(p));
    return a;
}
__device__ __forceinline__ void ldsm_x4(uint32_t (&r)[4], uint32_t addr) {
    asm volatile("ldmatrix.sync.aligned.m8n8.x4.shared.b16 {%0, %1, %2, %3}, [%4];"
                 : "=r"(r[0]), "=r"(r[1]), "=r"(r[2]), "=r"(r[3]) : "r"(addr));
}
__device__ __forceinline__ void mma16816(float (&d)[4], const uint32_t (&a)[4],
                                         uint32_t b0, uint32_t b1) {
    asm volatile(
        "mma.sync.aligned.m16n8k16.row.col.f32.bf16.bf16.f32 "
        "{%0, %1, %2, %3}, {%4, %5, %6, %7}, {%8, %9}, {%0, %1, %2, %3};"
        : "+f"(d[0]), "+f"(d[1]), "+f"(d[2]), "+f"(d[3])
        : "r"(a[0]), "r"(a[1]), "r"(a[2]), "r"(a[3]), "r"(b0), "r"(b1));
}
__device__ __forceinline__ void cp_async16(uint32_t saddr, const void* g) {
    asm volatile("cp.async.cg.shared.global [%0], [%1], 16;" :: "r"(saddr), "l"(g));
}
__device__ __forceinline__ void cp_async16z(uint32_t saddr, const void* g, uint32_t srcsz) {
    asm volatile("cp.async.cg.shared.global [%0], [%1], 16, %2;" :: "r"(saddr), "l"(g), "r"(srcsz));
}
// pack two f32 -> bf16x2 in one instruction (hi goes to upper half)
__device__ __forceinline__ uint32_t cvt_bf16x2(float hi, float lo) {
    uint32_t r;
    asm("cvt.rn.bf16x2.f32 %0, %1, %2;" : "=r"(r) : "f"(hi), "f"(lo));
    return r;
}

// ---------------- kernel: transpose x (NCHW -> NHWC fp32 + bf16 hi/lo) ----------------
__global__ __launch_bounds__(256) void k_transpose_x(const float* __restrict__ x) {
    __shared__ float tile[64*129];
    int bid = blockIdx.x;              // b*128 + h
    int b = bid >> 7, h = bid & 127;
    int t = threadIdx.x;
    const float* xp = x + ((size_t)b*64*HW) + (size_t)h*WW;
    for (int i = t; i < 64*128; i += 256) {
        int c = i >> 7, w = i & 127;
        tile[c*129 + w] = xp[(size_t)c*HW + w];
    }
    __syncthreads();
    float4* out4 = (float4*)g_xt;
    uint2* oh = (uint2*)g_xbh;
    uint2* ol = (uint2*)g_xbl;
    for (int i = t; i < 2048; i += 256) {
        int w = i >> 4, cq = i & 15;
        float4 v;
        v.x = tile[(cq*4+0)*129 + w];
        v.y = tile[(cq*4+1)*129 + w];
        v.z = tile[(cq*4+2)*129 + w];
        v.w = tile[(cq*4+3)*129 + w];
        size_t oidx = (size_t)(bid*128 + w)*16 + cq;
        out4[oidx] = v;
        uint32_t h01 = cvt_bf16x2(v.y, v.x);
        uint32_t h23 = cvt_bf16x2(v.w, v.z);
        float hix = __uint_as_float(h01 << 16);
        float hiy = __uint_as_float(h01 & 0xFFFF0000u);
        float hiz = __uint_as_float(h23 << 16);
        float hiw = __uint_as_float(h23 & 0xFFFF0000u);
        uint32_t l01 = cvt_bf16x2(v.y - hiy, v.x - hix);
        uint32_t l23 = cvt_bf16x2(v.w - hiw, v.z - hiz);
        oh[oidx] = make_uint2(h01, h23);
        ol[oidx] = make_uint2(l01, l23);
    }
}

// ---------------- kernel: weight split hi/lo (main + offset/mask) ----------------
__global__ __launch_bounds__(256) void k_wsplit(
    const float* __restrict__ weight,
    const float* __restrict__ w_off, const float* __restrict__ w_mask) {
    int idx = blockIdx.x*256 + threadIdx.x;
    if (idx < 9*128*72) {
        int k = idx / 9216;
        int r = idx - k*9216;
        int o = r / 72, c = r - o*72;
        float v = (c < 64) ? weight[(o*64 + c)*9 + k] : 0.f;
        __nv_bfloat16 hi = __float2bfloat16_rn(v);
        __nv_bfloat16 lo = __float2bfloat16_rn(v - __bfloat162float(hi));
        g_wbh[idx] = hi;
        g_wbl[idx] = lo;
    } else if (idx < 9*128*72 + 9*32*72) {
        int i2 = idx - 9*128*72;
        int k = i2 / 2304;
        int r = i2 - k*2304;
        int o = r / 72, c = r - o*72;
        float v = 0.f;
        if (c < 64) {
            if (o < 18)      v = w_off[(o*64 + c)*9 + k];
            else if (o < 27) v = w_mask[((o-18)*64 + c)*9 + k];
        }
        __nv_bfloat16 hi = __float2bfloat16_rn(v);
        __nv_bfloat16 lo = __float2bfloat16_rn(v - __bfloat162float(hi));
        g_obh[i2] = hi;
        g_obl[i2] = lo;
    }
}

// ---------------- kernel: offset/mask conv via bf16 split MMA + epi ----------------
// grid 512 (b*128+h), 256 threads. M=128 px, N=32 (27 used), K=576 over 9 taps.
#define OBUF 46080
#define OB_AHI 0
#define OB_ALO 18432
#define OB_BHI 36864
#define OB_BLO 41472
#define OSMEM_TOT 92160

__global__ __launch_bounds__(256, 2) void k_offset_mma(
    const float* __restrict__ b_off, const float* __restrict__ b_mask)
{
    extern __shared__ char sm[];
    uint32_t sb = smem_u32(sm);
    int t   = threadIdx.x;
    int wid = t >> 5, lane = t & 31;
    int bid = blockIdx.x;              // b*128 + h
    int b = bid >> 7, h = bid & 127;

    float acc[4][4];
    #pragma unroll
    for (int i = 0; i < 4; ++i)
        #pragma unroll
        for (int q = 0; q < 4; ++q) acc[i][q] = 0.f;

    int lrow = (lane & 7) + ((lane >> 3) & 1) * 8;
    int lcol = (lane & 16) ? 8 : 0;

    auto stage = [&](int kk) {
        uint32_t base = sb + (kk & 1) * OBUF;
        int ky = kk / 3, kx = kk % 3;
        int hy = h - 1 + ky;
        bool rowok = (unsigned)hy < 128u;
        int hyc = rowok ? hy : 0;
        const char* srcH = (const char*)g_xbh + ((size_t)((b*128 + hyc)*128)) * 128;
        const char* srcL = (const char*)g_xbl + ((size_t)((b*128 + hyc)*128)) * 128;
        #pragma unroll
        for (int j = 0; j < 8; ++j) {
            int i = t + j*256;
            int half = i >> 10;
            int r = i & 1023;
            int px = r >> 3, part = r & 7;
            int sx = px - 1 + kx;
            bool ok = rowok && ((unsigned)sx < 128u);
            int sxc = ok ? sx : 0;
            uint32_t srcsz = ok ? 16u : 0u;
            const char* src = (half ? srcL : srcH) + (size_t)sxc*128 + part*16;
            uint32_t dst = base + (half ? OB_ALO : OB_AHI) + px*144 + part*16;
            cp_async16z(dst, src, srcsz);
        }
        #pragma unroll
        for (int j = 0; j < 3; ++j) {
            int i = t + j*256;
            if (i < 576) {
                int half = (i >= 288);
                int r = half ? i - 288 : i;
                const char* src = (const char*)(half ? g_obl : g_obh) + (size_t)kk*4608 + r*16;
                uint32_t dst = base + (half ? OB_BLO : OB_BHI) + r*16;
                cp_async16(dst, src);
            }
        }
        asm volatile("cp.async.commit_group;");
    };

    stage(0);
    for (int k = 0; k < 9; ++k) {
        asm volatile("cp.async.wait_group 0;" ::: "memory");
        __syncthreads();
        if (k < 8) stage(k + 1);
        uint32_t base = sb + (k & 1) * OBUF;
        #pragma unroll
        for (int ks = 0; ks < 4; ++ks) {
            int kc = ks*16 + lcol;
            uint32_t ah[4], al[4];
            uint32_t aoff = (uint32_t)((wid*16 + lrow)*144 + kc*2);
            ldsm_x4(ah, base + OB_AHI + aoff);
            ldsm_x4(al, base + OB_ALO + aoff);
            #pragma unroll
            for (int bt = 0; bt < 2; ++bt) {
                uint32_t bh[4], bl[4];
                uint32_t boff = (uint32_t)((bt*16 + lrow)*144 + kc*2);
                ldsm_x4(bh, base + OB_BHI + boff);
                ldsm_x4(bl, base + OB_BLO + boff);
                mma16816(acc[2*bt],   ah, bh[0], bh[2]);
                mma16816(acc[2*bt+1], ah, bh[1], bh[3]);
                mma16816(acc[2*bt],   al, bh[0], bh[2]);
                mma16816(acc[2*bt+1], al, bh[1], bh[3]);
                mma16816(acc[2*bt],   ah, bl[0], bl[2]);
                mma16816(acc[2*bt+1], ah, bl[1], bl[3]);
            }
        }
    }

    __syncthreads();
    float* smo = (float*)sm;
    int qrow = lane >> 2, qcol = (lane & 3) * 2;
    #pragma unroll
    for (int oct = 0; oct < 4; ++oct) {
        int co = oct*8 + qcol;
        if (co < 27) {
            int px0 = wid*16 + qrow;
            smo[px0*28 + co]     = acc[oct][0];
            smo[(px0+8)*28 + co] = acc[oct][2];
            if (co + 1 < 27) {
                smo[px0*28 + co + 1]     = acc[oct][1];
                smo[(px0+8)*28 + co + 1] = acc[oct][3];
            }
        }
    }
    __syncthreads();

    if (t < 128) {
        int px = t;
        int pxg = ((b << 7) + h)*128 + px;
        #pragma unroll
        for (int kk = 0; kk < 9; ++kk) {
            float dy = smo[px*28 + 2*kk]   + b_off[2*kk];
            float dx = smo[px*28 + 2*kk+1] + b_off[2*kk+1];
            float mz = smo[px*28 + 18+kk]  + b_mask[kk];
            float m  = 1.0f / (1.0f + __expf(-mz));
            float py  = (float)(h  - 1 + kk/3) + dy;
            float pxx = (float)(px - 1 + kk%3) + dx;
            float y0f = floorf(py), x0f = floorf(pxx);
            float ly = py - y0f, lx = pxx - x0f;
            int y0 = (int)y0f, x0i = (int)x0f;
            int y1 = y0 + 1,  x1i = x0i + 1;
            float w00 = (1.f-ly)*(1.f-lx)*m;
            float w01 = (1.f-ly)*lx*m;
            float w10 = ly*(1.f-lx)*m;
            float w11 = ly*lx*m;
            if (y0  < 0 || y0  > 127) { w00 = 0.f; w01 = 0.f; }
            if (y1  < 0 || y1  > 127) { w10 = 0.f; w11 = 0.f; }
            if (x0i < 0 || x0i > 127) { w00 = 0.f; w10 = 0.f; }
            if (x1i < 0 || x1i > 127) { w01 = 0.f; w11 = 0.f; }
            int y0c = min(max(y0, 0), 127),  y1c = min(max(y1, 0), 127);
            int x0c = min(max(x0i, 0), 127), x1c = min(max(x1i, 0), 127);
            g_ppi[kk*NPX + pxg] = y0c | (y1c << 8) | (x0c << 16) | (x1c << 24);
            g_ppw[kk*NPX + pxg] = make_float4(w00, w01, w10, w11);
        }
    }
}

// ---------------- kernel: deformable sampling + bf16 split mma.sync GEMM ----------------
// grid 1024 (b, h, half-row), 256 threads. Block tile: M=64 px, N=128 out, K=576.
// A and B double-buffered; interleaved pipeline (loads tap k+1 under MMA tap k).
// Sampling layout: 16 lanes per pixel (scq = t&15, px = t>>4 + 16j) -> corner LDG.128
// warp-wide = 4 L1 wavefronts (vs 8 for the quad layout). pc[] preloaded per iteration.
#define DA_STRIDE 18432      // per A buffer: HI 9216 + LO 9216
#define DA_LO 9216
#define DB_OFF 36864
#define DB_STRIDE 36864      // per B buffer: HI 18432 + LO 18432
#define DB_LO 18432
#define DSMEM_TOT 110592

__global__ __launch_bounds__(256, 2) void k_deform_mma(float* __restrict__ out) {
    extern __shared__ char sm[];
    uint32_t sb = smem_u32(sm);
    int t    = threadIdx.x;
    int wid  = t >> 5, lane = t & 31;
    int bid  = blockIdx.x;                 // b*256 + h*2 + half
    int b    = bid >> 8;
    int rem  = bid & 255;
    int h    = rem >> 1, half = rem & 1;
    const float* xb = g_xt + ((size_t)b << 20);

    int warp_m = wid & 1;
    int warp_n = wid >> 1;
    int m0base = warp_m * 32;
    int n0base = warp_n * 32;

    float acc[2][4][4];
    #pragma unroll
    for (int i = 0; i < 2; ++i)
        #pragma unroll
        for (int j = 0; j < 4; ++j)
            #pragma unroll
            for (int q = 0; q < 4; ++q) acc[i][j][q] = 0.f;

    int lrow = (lane & 7) + ((lane >> 3) & 1) * 8;
    int lcol = (lane & 16) ? 8 : 0;

    int scq = t & 15;            // channel quad (16 B)
    int spx0 = t >> 4;           // base pixel 0..15; px = spx0 + 16*j
    int pxbase = (((b << 7) + h) << 7) + half*64;

    // stage B tap kk into B buffer kk&1 via cp.async (shared-space dst)
    auto stage_B = [&](int kk) {
        uint32_t bbuf = sb + DB_OFF + (kk & 1) * DB_STRIDE;
        const char* srcH = (const char*)(g_wbh + kk*9216);
        const char* srcL = (const char*)(g_wbl + kk*9216);
        #pragma unroll
        for (int j = 0; j < 5; ++j) {
            int i = t + j*256;
            if (i < 1152) {
                cp_async16(bbuf + i*16, srcH + i*16);
                cp_async16(bbuf + DB_LO + i*16, srcL + i*16);
            }
        }
        asm volatile("cp.async.commit_group;");
    };

    // interp chunk, split (bf16x2 cvt), store into A buffer at byte offset abuf_off (generic)
    auto store_sample = [&](int abuf_off, int px, float4 a, float4 bb, float4 cc, float4 dd,
                            float4 wg) {
        float4 v;
        v.x = wg.x*a.x + wg.y*bb.x + wg.z*cc.x + wg.w*dd.x;
        v.y = wg.x*a.y + wg.y*bb.y + wg.z*cc.y + wg.w*dd.y;
        v.z = wg.x*a.z + wg.y*bb.z + wg.z*cc.z + wg.w*dd.z;
        v.w = wg.x*a.w + wg.y*bb.w + wg.z*cc.w + wg.w*dd.w;
        uint32_t h01 = cvt_bf16x2(v.y, v.x);
        uint32_t h23 = cvt_bf16x2(v.w, v.z);
        float hix = __uint_as_float(h01 << 16);
        float hiy = __uint_as_float(h01 & 0xFFFF0000u);
        float hiz = __uint_as_float(h23 << 16);
        float hiw = __uint_as_float(h23 & 0xFFFF0000u);
        uint32_t l01 = cvt_bf16x2(v.y - hiy, v.x - hix);
        uint32_t l23 = cvt_bf16x2(v.w - hiw, v.z - hiz);
        int off = px*144 + scq*8;
        *(uint2*)(sm + abuf_off + off) = make_uint2(h01, h23);
        *(uint2*)(sm + abuf_off + DA_LO + off) = make_uint2(l01, l23);
    };

    // prologue: B(0) async + full sample of tap 0 into A buffer 0 (byte offset 0)
    stage_B(0);
    {
        #pragma unroll
        for (int j = 0; j < 4; ++j) {
            int px = spx0 + 16*j;
            int    pc = g_ppi[pxbase + px];
            float4 wg = g_ppw[pxbase + px];
            int y0 =  pc        & 255;
            int y1 = (pc >>  8) & 255;
            int x0 = (pc >> 16) & 255;
            int x1 = (pc >> 24) & 255;
            float4 a  = *((const float4*)(xb + (size_t)(((y0<<7)+x0)<<6)) + scq);
            float4 bb = *((const float4*)(xb + (size_t)(((y0<<7)+x1)<<6)) + scq);
            float4 cc = *((const float4*)(xb + (size_t)(((y1<<7)+x0)<<6)) + scq);
            float4 dd = *((const float4*)(xb + (size_t)(((y1<<7)+x1)<<6)) + scq);
            store_sample(0, px, a, bb, cc, dd, wg);
        }
    }

    for (int k = 0; k < 9; ++k) {
        asm volatile("cp.async.wait_group 0;" ::: "memory");   // B(k) landed
        __syncthreads();                                       // A(k) published; prev reads of buf k^1 done
        if (k < 8) stage_B(k + 1);

        uint32_t abase = sb + (k & 1) * DA_STRIDE;             // shared addr (ldsm)
        uint32_t bbase = sb + DB_OFF + (k & 1) * DB_STRIDE;    // shared addr (ldsm)
        int an_off = ((k + 1) & 1) * DA_STRIDE;                // BYTE OFFSET (generic stores)

        bool do_sample = (k < 8);
        int ppb = (k + 1)*NPX + pxbase;
        int pcv[4];
        if (do_sample) {
            #pragma unroll
            for (int g = 0; g < 4; ++g)
                pcv[g] = g_ppi[ppb + spx0 + 16*g];
        }

        #pragma unroll
        for (int j = 0; j < 4; ++j) {
            // (1) issue next-tap corner loads for pixel j (latency hidden under MMA)
            float4 a, bb, cc, dd, wg;
            int px = spx0 + 16*j;
            if (do_sample) {
                int pc = pcv[j];
                int y0 =  pc        & 255;
                int y1 = (pc >>  8) & 255;
                int x0 = (pc >> 16) & 255;
                int x1 = (pc >> 24) & 255;
                a  = *((const float4*)(xb + (size_t)(((y0<<7)+x0)<<6)) + scq);
                bb = *((const float4*)(xb + (size_t)(((y0<<7)+x1)<<6)) + scq);
                cc = *((const float4*)(xb + (size_t)(((y1<<7)+x0)<<6)) + scq);
                dd = *((const float4*)(xb + (size_t)(((y1<<7)+x1)<<6)) + scq);
                wg = g_ppw[ppb + px];
            }

            // (2) MMA kstep j on buffers k
            {
                int kc = j*16 + lcol;
                uint32_t ah[2][4], al[2][4];
                #pragma unroll
                for (int mt = 0; mt < 2; ++mt) {
                    uint32_t aoff = (uint32_t)((m0base + mt*16 + lrow)*144 + kc*2);
                    ldsm_x4(ah[mt], abase + aoff);
                    ldsm_x4(al[mt], abase + DA_LO + aoff);
                }
                #pragma unroll
                for (int ng = 0; ng < 2; ++ng) {
                    uint32_t bh[4], bl[4];
                    uint32_t boff = (uint32_t)((n0base + ng*16 + lrow)*144 + kc*2);
                    ldsm_x4(bh, bbase + boff);
                    ldsm_x4(bl, bbase + DB_LO + boff);
                    #pragma unroll
                    for (int mt = 0; mt < 2; ++mt) {
                        mma16816(acc[mt][2*ng],   ah[mt], bh[0], bh[2]);
                        mma16816(acc[mt][2*ng+1], ah[mt], bh[1], bh[3]);
                        mma16816(acc[mt][2*ng],   al[mt], bh[0], bh[2]);
                        mma16816(acc[mt][2*ng+1], al[mt], bh[1], bh[3]);
                        mma16816(acc[mt][2*ng],   ah[mt], bl[0], bl[2]);
                        mma16816(acc[mt][2*ng+1], ah[mt], bl[1], bl[3]);
                    }
                }
            }

            // (3) consume loads: interp, split, store into next A buffer (byte offset)
            if (do_sample)
                store_sample(an_off, px, a, bb, cc, dd, wg);
        }
    }

    // ---- epilogue: frags -> smem [o][px] (pitch 68), coalesced stores ----
    __syncthreads();
    float* smo = (float*)sm;
    int qrow = lane >> 2, qcol = (lane & 3) * 2;
    #pragma unroll
    for (int mt = 0; mt < 2; ++mt) {
        #pragma unroll
        for (int nt = 0; nt < 4; ++nt) {
            int px0 = m0base + mt*16 + qrow;
            int o0  = n0base + nt*8 + qcol;
            smo[ o0     *68 + px0    ] = acc[mt][nt][0];
            smo[(o0 + 1)*68 + px0    ] = acc[mt][nt][1];
            smo[ o0     *68 + px0 + 8] = acc[mt][nt][2];
            smo[(o0 + 1)*68 + px0 + 8] = acc[mt][nt][3];
        }
    }
    __syncthreads();
    float* op = out + ((size_t)b*128)*16384 + (size_t)h*128 + half*64;
    #pragma unroll
    for (int j = 0; j < 8; ++j) {
        int idx = t + j*256;
        int o = idx >> 4, pq = idx & 15;
        float4 v = *(const float4*)(smo + o*68 + pq*4);
        *(float4*)(op + (size_t)o*16384 + pq*4) = v;
    }
}

// ---------------- launch ----------------
extern "C" void kernel_launch(void* const* d_in, const int* in_sizes, int n_in,
                              void* d_out, int out_size) {
    const float* x      = (const float*)d_in[0];
    const float* w_off  = (const float*)d_in[1];
    const float* b_off  = (const float*)d_in[2];
    const float* w_mask = (const float*)d_in[3];
    const float* b_mask = (const float*)d_in[4];
    const float* weight = (const float*)d_in[5];
    float* out = (float*)d_out;

    (void)cudaFuncSetAttribute(k_deform_mma, cudaFuncAttributeMaxDynamicSharedMemorySize, DSMEM_TOT);
    (void)cudaFuncSetAttribute(k_offset_mma, cudaFuncAttributeMaxDynamicSharedMemorySize, OSMEM_TOT);

    k_transpose_x<<<512, 256>>>(x);
    k_wsplit<<<(9*128*72 + 9*32*72 + 255)/256, 256>>>(weight, w_off, w_mask);
    k_offset_mma<<<512, 256, OSMEM_TOT>>>(b_off, b_mask);
    k_deform_mma<<<1024, 256, DSMEM_TOT>>>(out);
}